// round 14
// baseline (speedup 1.0000x reference)
#include <cuda_runtime.h>
#include <cuda_fp16.h>
#include <cstdint>
#include <math.h>

#define N_NODES 10000
#define N_EDGES 160000
#define F_DIM   64
#define NHEAD   4
#define N_PAD   10048

// ---------------- scratch (device globals; zero-initialized at load) --------
__device__ uint4   g_feat[N_NODES * 64];   // fp16 interleaved {rad01,rad23,tan01,tan23}
__device__ float4  g_score_r[N_NODES];
__device__ float4  g_score_t[N_NODES];
__device__ float   g_vr[NHEAD * F_DIM];
__device__ float   g_vt[NHEAD * F_DIM];
__device__ float   g_scale;
__device__ float   g_tconst[2 * NHEAD];
__device__ int     g_indeg[N_NODES];       // reset by k_gather each pass
__device__ int     g_offs[N_NODES];
__device__ int     g_cursor[N_NODES];
__device__ int     g_se[N_EDGES];          // sorted-by-receiver sender id
__device__ int     g_eid[N_EDGES];         // sorted-by-receiver original edge id
__device__ int     g_alloc;                // reset by k_gather each pass
__device__ uint32_t g_wt[8 * 64 * 64];     // tf32 proj weights [bc][f][g]
__device__ uint32_t g_wo[64 * 64];         // tf32 w_out [k][c]
__device__ uint4   g_xt[N_PAD * 16];       // tf32 x [n][f]
__device__ uint4   g_p[N_PAD * 16];        // tf32 message P [n][k]

__device__ __forceinline__ float softplusf(float z) {
    return z > 20.f ? z : log1pf(__expf(z));
}

__device__ __forceinline__ uint32_t f2tf32(float v) {
    uint32_t u;
    asm("cvt.rna.tf32.f32 %0, %1;" : "=r"(u) : "f"(v));
    return u;
}

__device__ __forceinline__ void mma_tf32(float4& c,
                                         uint32_t a0, uint32_t a1, uint32_t a2, uint32_t a3,
                                         uint32_t b0, uint32_t b1) {
    asm volatile(
        "mma.sync.aligned.m16n8k8.row.col.f32.tf32.tf32.f32 "
        "{%0,%1,%2,%3}, {%4,%5,%6,%7}, {%8,%9}, {%0,%1,%2,%3};"
        : "+f"(c.x), "+f"(c.y), "+f"(c.z), "+f"(c.w)
        : "r"(a0), "r"(a1), "r"(a2), "r"(a3), "r"(b0), "r"(b1));
}

// ---------------- K0: hist + cvts (x, weights, wout) + vector fold ----------
__global__ void k_pre(const float* __restrict__ x,
                      const int* __restrict__ eidx,
                      const float* __restrict__ wproj,
                      const float* __restrict__ rW,
                      const float* __restrict__ tW,
                      const float* __restrict__ wout,
                      const float* __restrict__ rs,
                      const float* __restrict__ ts,
                      const float* __restrict__ rdls,
                      const float* __restrict__ tbias,
                      const float* __restrict__ tweight) {
    int i = blockIdx.x * blockDim.x + threadIdx.x;
    if (i < N_EDGES) atomicAdd(&g_indeg[eidx[N_EDGES + i]], 1);

    uint32_t* xt = (uint32_t*)g_xt;
    for (int j = i; j < N_NODES * F_DIM; j += N_EDGES) xt[j] = f2tf32(x[j]);
    if (i < 8 * 4096) {
        int bc = i >> 12, within = i & 4095;
        const float* src = (bc < 4) ? (rW + bc * 4096) : (tW + (bc - 4) * 4096);
        g_wt[i] = f2tf32(src[within]);
    }
    if (i < 4096) g_wo[i] = f2tf32(wout[i]);

    if (blockIdx.x != 0) return;
    int t = threadIdx.x;
    int h = t >> 6, f = t & 63;
    const float* W  = wproj + h * F_DIM * F_DIM + f * F_DIM;
    const float* rv = rs + h * F_DIM;
    const float* tv = ts + h * F_DIM;
    float ar = 0.f, at = 0.f;
#pragma unroll
    for (int g = 0; g < F_DIM; g++) { ar += W[g] * rv[g]; at += W[g] * tv[g]; }
    g_vr[t] = ar;
    g_vt[t] = at;
    if (t == 0) g_scale = softplusf(rdls[0]);
    if (t < NHEAD)          g_tconst[t] = tbias[t];
    else if (t < 2 * NHEAD) g_tconst[t] = tweight[t - NHEAD];
}

// ---------------- K1: range allocation + fp32 scalar scores -----------------
__global__ void k_base_score(const float* __restrict__ x) {
    int idx = blockIdx.x * blockDim.x + threadIdx.x;
    if (idx < N_NODES) {
        int b = atomicAdd(&g_alloc, g_indeg[idx]);
        g_offs[idx]   = b;
        g_cursor[idx] = b;
    }
    if (idx < N_NODES * 8) {
        int n = idx >> 3, sub = idx & 7;
        int hh = sub & 3;
        bool isR = sub < 4;
        const float* v = (isR ? g_vr : g_vt) + hh * F_DIM;
        const float* xr = x + n * F_DIM;
        float s = 0.f;
#pragma unroll
        for (int f = 0; f < F_DIM; f++) s += xr[f] * v[f];
        float* dst = isR ? (float*)g_score_r : (float*)g_score_t;
        dst[n * NHEAD + hh] = s;
    }
}

// ---------------- K2: tensor-core GEMM + edge sort scatter ------------------
#define XS_STRIDE 68
#define WS_STRIDE 72
__global__ void __launch_bounds__(256) k_node_mma(const int* __restrict__ eidx) {
    __shared__ uint32_t xs[64 * XS_STRIDE];
    __shared__ uint32_t ws[64 * WS_STRIDE];
    int t  = threadIdx.x;
    int n0 = blockIdx.x * 64;
    int bc = blockIdx.y;

    int gid = (bc * gridDim.x + blockIdx.x) * 256 + t;
    if (gid < N_EDGES) {
        int s = eidx[gid];
        int r = eidx[N_EDGES + gid];
        int pos = atomicAdd(&g_cursor[r], 1);
        g_se[pos]  = s;
        g_eid[pos] = gid;
    }

    const uint4* xsrc = g_xt + n0 * 16;
#pragma unroll
    for (int i = 0; i < 4; i++) {
        int idx4 = i * 256 + t;
        int n = idx4 >> 4, gq = idx4 & 15;
        uint4 v = xsrc[idx4];
        *(uint4*)(xs + n * XS_STRIDE + gq * 4) = v;
    }
    const uint32_t* wsrc = g_wt + bc * 4096;
#pragma unroll
    for (int i = 0; i < 4; i++) {
        int idx4 = i * 256 + t;
        int f = idx4 >> 4, gq = idx4 & 15;
        uint4 v = ((const uint4*)wsrc)[idx4];
        *(uint4*)(ws + f * WS_STRIDE + gq * 4) = v;
    }
    __syncthreads();

    int w = t >> 5, lane = t & 31;
    int g4 = lane >> 2, tig = lane & 3;
    int nt = w & 3;
    int cb = (w >> 2) * 4;
    const uint32_t* xrow0 = xs + (nt * 16 + g4) * XS_STRIDE;
    const uint32_t* xrow1 = xrow0 + 8 * XS_STRIDE;

    float4 acc[4];
#pragma unroll
    for (int ct = 0; ct < 4; ct++) acc[ct] = make_float4(0.f, 0.f, 0.f, 0.f);
#pragma unroll
    for (int k0 = 0; k0 < 64; k0 += 8) {
        uint32_t a0 = xrow0[k0 + tig];
        uint32_t a1 = xrow1[k0 + tig];
        uint32_t a2 = xrow0[k0 + tig + 4];
        uint32_t a3 = xrow1[k0 + tig + 4];
#pragma unroll
        for (int ct = 0; ct < 4; ct++) {
            int gcol = (cb + ct) * 8 + g4;
            uint32_t b0 = ws[(k0 + tig) * WS_STRIDE + gcol];
            uint32_t b1 = ws[(k0 + tig + 4) * WS_STRIDE + gcol];
            mma_tf32(acc[ct], a0, a1, a2, a3, b0, b1);
        }
    }

    __half2* fw = (__half2*)g_feat;
    int wordbase = (bc < 4) ? 0 : 2;
    int cbase = (bc & 3) * 64;
    int n_a = n0 + nt * 16 + g4;
    int n_b = n_a + 8;
#pragma unroll
    for (int ct = 0; ct < 4; ct++) {
        int c = cbase + (cb + ct) * 8 + tig * 2;
        int tcol = c >> 2;
        int word = wordbase + ((c & 2) >> 1);
        __half2 h01 = __floats2half2_rn(acc[ct].x, acc[ct].y);
        __half2 h23 = __floats2half2_rn(acc[ct].z, acc[ct].w);
        if (n_a < N_NODES) fw[(n_a * 64 + tcol) * 4 + word] = h01;
        if (n_b < N_NODES) fw[(n_b * 64 + tcol) * 4 + word] = h23;
    }
}

// ---------------- K3: fused exp + gather -> message P (tf32) ----------------
__global__ void __launch_bounds__(64) k_gather(const float* __restrict__ elen) {
    __shared__ int    sm_s[64];
    __shared__ float2 sm_w[64][NHEAD];
    __shared__ float4 tmp[64];
    int n = blockIdx.x;
    int t = threadIdx.x;
    int h = t >> 4;
    int base = g_offs[n];
    int deg  = g_indeg[n];

    float4 srr = g_score_r[n];
    float4 str = g_score_t[n];
    float tb0 = g_tconst[0], tb1 = g_tconst[1], tb2 = g_tconst[2], tb3 = g_tconst[3];
    float tw0 = g_tconst[4], tw1 = g_tconst[5], tw2 = g_tconst[6], tw3 = g_tconst[7];
    float scale = g_scale;

    float4 accr = make_float4(0.f, 0.f, 0.f, 0.f);
    float4 acct = make_float4(0.f, 0.f, 0.f, 0.f);
    float sdr = 0.f, sdt = 0.f;

    for (int c0 = 0; c0 < deg; c0 += 64) {
        int cnt = min(64, deg - c0);
        if (t < cnt) {
            int j = base + c0 + t;
            int s = g_se[j];
            float len = elen[g_eid[j]];
            float4 srs = g_score_r[s];
            float4 sts = g_score_t[s];
            float it0 = 1.f / (softplusf(tb0 + tw0 * len) + 1e-4f);
            float it1 = 1.f / (softplusf(tb1 + tw1 * len) + 1e-4f);
            float it2 = 1.f / (softplusf(tb2 + tw2 * len) + 1e-4f);
            float it3 = 1.f / (softplusf(tb3 + tw3 * len) + 1e-4f);
            float sl = scale * len;
            sm_s[t] = s;
            sm_w[t][0] = make_float2(__expf((srs.x - srr.x - sl) * it0), __expf(sts.x - str.x));
            sm_w[t][1] = make_float2(__expf((srs.y - srr.y - sl) * it1), __expf(sts.y - str.y));
            sm_w[t][2] = make_float2(__expf((srs.z - srr.z - sl) * it2), __expf(sts.z - str.z));
            sm_w[t][3] = make_float2(__expf((srs.w - srr.w - sl) * it3), __expf(sts.w - str.w));
        }
        __syncthreads();

#define GATHER_ONE(C)                                                          \
        {                                                                      \
            float2 w2 = sm_w[C][h];                                            \
            uint4 f4 = g_feat[sm_s[C] * 64 + t];                               \
            float2 r0 = __half22float2(*(__half2*)&f4.x);                      \
            float2 r1 = __half22float2(*(__half2*)&f4.y);                      \
            float2 t0 = __half22float2(*(__half2*)&f4.z);                      \
            float2 t1 = __half22float2(*(__half2*)&f4.w);                      \
            accr.x += w2.x * r0.x; accr.y += w2.x * r0.y;                      \
            accr.z += w2.x * r1.x; accr.w += w2.x * r1.y;                      \
            acct.x += w2.y * t0.x; acct.y += w2.y * t0.y;                      \
            acct.z += w2.y * t1.x; acct.w += w2.y * t1.y;                      \
            sdr += w2.x; sdt += w2.y;                                          \
        }
        int half1 = cnt >> 1;
        int c1 = 0, c2 = half1;
        for (; c1 < half1; c1++, c2++) {
            GATHER_ONE(c1);
            GATHER_ONE(c2);
        }
        for (; c2 < cnt; c2++) GATHER_ONE(c2);
#undef GATHER_ONE
        __syncthreads();
    }

    float4 res = make_float4(0.f, 0.f, 0.f, 0.f);
    if (deg > 0) {
        float ir = 1.f / sdr;
        float it = 1.f / sdt;
        uint4 f4 = g_feat[n * 64 + t];
        float2 r0 = __half22float2(*(__half2*)&f4.x);
        float2 r1 = __half22float2(*(__half2*)&f4.y);
        float2 t0 = __half22float2(*(__half2*)&f4.z);
        float2 t1 = __half22float2(*(__half2*)&f4.w);
        res.x = accr.x * ir + acct.x * it - r0.x - t0.x;
        res.y = accr.y * ir + acct.y * it - r0.y - t0.y;
        res.z = accr.z * ir + acct.z * it - r1.x - t1.x;
        res.w = accr.w * ir + acct.w * it - r1.y - t1.y;
    }
    tmp[t] = res;
    __syncthreads();
    // head-mean -> tf32 message P[n][0..63]
    if (t < 16) {
        float4 a = tmp[t], b = tmp[t + 16], c = tmp[t + 32], d = tmp[t + 48];
        uint4 pv;
        pv.x = f2tf32((a.x + b.x + c.x + d.x) * 0.25f);
        pv.y = f2tf32((a.y + b.y + c.y + d.y) * 0.25f);
        pv.z = f2tf32((a.z + b.z + c.z + d.z) * 0.25f);
        pv.w = f2tf32((a.w + b.w + c.w + d.w) * 0.25f);
        g_p[n * 16 + t] = pv;
    }

    // reset pass-state for the next graph replay
    if (t == 0) {
        g_indeg[n] = 0;
        if (n == 0) g_alloc = 0;
    }
}

// ---------------- K4: out = x + P @ w_out (tensor cores) --------------------
__global__ void __launch_bounds__(256) k_out(const float* __restrict__ x,
                                             float* __restrict__ out) {
    __shared__ uint32_t xs[64 * XS_STRIDE];
    __shared__ uint32_t ws[64 * WS_STRIDE];
    int t  = threadIdx.x;
    int n0 = blockIdx.x * 64;

    const uint4* psrc = g_p + n0 * 16;
#pragma unroll
    for (int i = 0; i < 4; i++) {
        int idx4 = i * 256 + t;
        int n = idx4 >> 4, gq = idx4 & 15;
        uint4 v = psrc[idx4];
        *(uint4*)(xs + n * XS_STRIDE + gq * 4) = v;
    }
#pragma unroll
    for (int i = 0; i < 4; i++) {
        int idx4 = i * 256 + t;
        int f = idx4 >> 4, gq = idx4 & 15;
        uint4 v = ((const uint4*)g_wo)[idx4];
        *(uint4*)(ws + f * WS_STRIDE + gq * 4) = v;
    }
    __syncthreads();

    int w = t >> 5, lane = t & 31;
    int g4 = lane >> 2, tig = lane & 3;
    int nt = w & 3;
    int cb = (w >> 2) * 4;
    const uint32_t* xrow0 = xs + (nt * 16 + g4) * XS_STRIDE;
    const uint32_t* xrow1 = xrow0 + 8 * XS_STRIDE;

    float4 acc[4];
#pragma unroll
    for (int ct = 0; ct < 4; ct++) acc[ct] = make_float4(0.f, 0.f, 0.f, 0.f);
#pragma unroll
    for (int k0 = 0; k0 < 64; k0 += 8) {
        uint32_t a0 = xrow0[k0 + tig];
        uint32_t a1 = xrow1[k0 + tig];
        uint32_t a2 = xrow0[k0 + tig + 4];
        uint32_t a3 = xrow1[k0 + tig + 4];
#pragma unroll
        for (int ct = 0; ct < 4; ct++) {
            int gcol = (cb + ct) * 8 + g4;
            uint32_t b0 = ws[(k0 + tig) * WS_STRIDE + gcol];
            uint32_t b1 = ws[(k0 + tig + 4) * WS_STRIDE + gcol];
            mma_tf32(acc[ct], a0, a1, a2, a3, b0, b1);
        }
    }

    int n_a = n0 + nt * 16 + g4;
    int n_b = n_a + 8;
#pragma unroll
    for (int ct = 0; ct < 4; ct++) {
        int c = cb * 8 + ct * 8 + tig * 2;
        if (n_a < N_NODES) {
            float2 xv = *(const float2*)(x + n_a * F_DIM + c);
            *(float2*)(out + n_a * F_DIM + c) = make_float2(xv.x + acc[ct].x, xv.y + acc[ct].y);
        }
        if (n_b < N_NODES) {
            float2 xv = *(const float2*)(x + n_b * F_DIM + c);
            *(float2*)(out + n_b * F_DIM + c) = make_float2(xv.x + acc[ct].z, xv.y + acc[ct].w);
        }
    }
}

// ---------------- launch -----------------------------------------------------
extern "C" void kernel_launch(void* const* d_in, const int* in_sizes, int n_in,
                              void* d_out, int out_size) {
    const float* x      = (const float*)d_in[0];
    const int*   eidx   = (const int*)d_in[1];
    // d_in[2] = edge_vec : unused by the reference math
    const float* elen   = (const float*)d_in[3];
    const float* wproj  = (const float*)d_in[4];
    const float* rW     = (const float*)d_in[5];
    const float* tW     = (const float*)d_in[6];
    const float* rs     = (const float*)d_in[7];
    const float* ts     = (const float*)d_in[8];
    const float* rdls   = (const float*)d_in[9];
    const float* tbias  = (const float*)d_in[10];
    const float* tweight= (const float*)d_in[11];
    const float* wout   = (const float*)d_in[12];
    float* out = (float*)d_out;

    k_pre<<<(N_EDGES + 255) / 256, 256>>>(x, eidx, wproj, rW, tW, wout,
                                          rs, ts, rdls, tbias, tweight);
    k_base_score<<<(N_NODES * 8 + 255) / 256, 256>>>(x);
    dim3 ggrid((N_NODES + 63) / 64, 8);
    k_node_mma<<<ggrid, 256>>>(eidx);
    k_gather<<<N_NODES, 64>>>(elen);
    k_out<<<(N_NODES + 63) / 64, 256>>>(x, out);
}